// round 9
// baseline (speedup 1.0000x reference)
#include <cuda_runtime.h>
#include <cuda.h>
#include <cstring>

#define C    256
#define CH   128
#define HWn  262144
#define HW4  65536
#define SEGS 16
#define SEG_F4 4096   // HW4 / SEGS
#define EPS  1e-5f

// k3 tiling: 32 pixels per tile, double-buffered cp.async loads + TMA bulk stores
#define TP     32
#define TP4    8
#define TILE_F  (C * TP)       // 8192 floats = 32 KB
#define NTILES  (HWn / TP)     // 8192 tiles

__device__ float d_partials[C * SEGS];
__device__ float d_g[C];
__device__ float d_v[C];
__device__ float d_b0;

// ---------------- Kernel 1: per-channel spatial sums ------------------------------
__global__ void k1_sums(const float4* __restrict__ x4) {
    const int c = blockIdx.y, seg = blockIdx.x, t = threadIdx.x;
    const float4* xc = x4 + (size_t)c * HW4 + (size_t)seg * SEG_F4;
    float s = 0.f;
#pragma unroll
    for (int j = 0; j < 16; j++) {
        float4 u = xc[t + j * 256];
        s += (u.x + u.y) + (u.z + u.w);
    }
    __shared__ float red[256];
    red[t] = s;
    __syncthreads();
    for (int off = 128; off > 0; off >>= 1) {
        if (t < off) red[t] += red[t + off];
        __syncthreads();
    }
    if (t == 0) d_partials[c * SEGS + seg] = red[0];
}

// ---------------- Kernel 2: all the tiny algebra (1 block) ------------------------
__global__ void k2_scalars(const float* __restrict__ cv1w, const float* __restrict__ cv1b,
                           const float* __restrict__ cv3w, const float* __restrict__ cv3b,
                           const float* __restrict__ lng,  const float* __restrict__ lnb,
                           const float* __restrict__ sp1w, const float* __restrict__ sp1b,
                           const float* __restrict__ sp2w, const float* __restrict__ sp2b) {
    __shared__ float S[C];
    __shared__ float ybuf[CH];
    __shared__ float s2[CH];
    __shared__ float wsm[CH];
    __shared__ float red[256];
    const int t = threadIdx.x;

    {
        float s = 0.f;
#pragma unroll
        for (int j = 0; j < SEGS; j++) s += d_partials[t * SEGS + j];
        S[t] = s;
    }
    __syncthreads();

    if (t < CH) {
        float a = 0.f;
        for (int c = 0; c < C; c++) a += cv1w[t * C + c] * S[c];
        ybuf[t] = a + (float)HWn * cv1b[t];
    } else {
        const int u = t - CH;
        float a = 0.f;
        for (int c = 0; c < C; c++) a += sp2w[u * C + c] * S[c];
        s2[u] = a * (1.f / (float)HWn) + sp2b[u];
    }
    __syncthreads();

    float zv = cv3b[t];
    for (int c = 0; c < CH; c++) zv += cv3w[t * CH + c] * ybuf[c];

    red[t] = zv;
    __syncthreads();
    for (int off = 128; off > 0; off >>= 1) {
        if (t < off) red[t] += red[t + off];
        __syncthreads();
    }
    const float mu = red[0] * (1.f / (float)C);
    __syncthreads();
    red[t] = zv * zv;
    __syncthreads();
    for (int off = 128; off > 0; off >>= 1) {
        if (t < off) red[t] += red[t + off];
        __syncthreads();
    }
    const float var = red[0] * (1.f / (float)C) - mu * mu;
    __syncthreads();

    const float zn = (zv - mu) * rsqrtf(var + EPS) * lng[t] + lnb[t];
    d_g[t] = 1.f / (1.f + expf(-zn));

    red[t] = (t < CH) ? s2[t] : -1e30f;
    __syncthreads();
    for (int off = 128; off > 0; off >>= 1) {
        if (t < off) red[t] = fmaxf(red[t], red[t + off]);
        __syncthreads();
    }
    const float mx = red[0];
    __syncthreads();
    red[t] = (t < CH) ? expf(s2[t] - mx) : 0.f;
    __syncthreads();
    for (int off = 128; off > 0; off >>= 1) {
        if (t < off) red[t] += red[t + off];
        __syncthreads();
    }
    const float denom = red[0];
    __syncthreads();
    if (t < CH) wsm[t] = expf(s2[t] - mx) / denom;
    __syncthreads();

    {
        float vv = 0.f;
        for (int c_ = 0; c_ < CH; c_++) vv += wsm[c_] * sp1w[c_ * C + t];
        d_v[t] = vv;
    }
    if (t == 0) {
        float b0 = 0.f;
        for (int c_ = 0; c_ < CH; c_++) b0 += wsm[c_] * sp1b[c_];
        d_b0 = b0;
    }
}

// ---------------- Kernel 3: pipelined fused yb + output (TMA bulk stores) ---------
__device__ __forceinline__ void k3_prefetch(const float4* __restrict__ x4,
                                            float* buf, int tile, int t) {
    unsigned dst_base = (unsigned)__cvta_generic_to_shared(buf);
    const int base4 = tile * TP4;
#pragma unroll
    for (int j = 0; j < 8; j++) {
        int i4 = t + j * 256;
        int c = i4 >> 3, p4 = i4 & 7;
        const float4* src = x4 + (size_t)c * HW4 + base4 + p4;
        unsigned dst = dst_base + i4 * 16;
        asm volatile("cp.async.cg.shared.global [%0], [%1], 16;\n" :: "r"(dst), "l"(src));
    }
    asm volatile("cp.async.commit_group;\n");
}

__global__ __launch_bounds__(256, 3)
void k3_out(const float4* __restrict__ x4, float4* __restrict__ out4,
            int grid_stride, const __grid_constant__ CUtensorMap tmap, int use_tma) {
    extern __shared__ __align__(1024) float sm[];
    float* buf0 = sm;                    // TILE_F (32KB, 1024-aligned)
    float* buf1 = sm + TILE_F;           // TILE_F
    float* sv   = sm + 2 * TILE_F;       // C
    float* sg   = sv + C;                // C
    float* part = sg + C;                // 256
    float* sy   = part + 256;            // TP

    const int t = threadIdx.x;
    sv[t] = d_v[t];
    sg[t] = d_g[t];
    const float b0 = d_b0;

    int tile = blockIdx.x;
    if (tile >= NTILES) return;
    k3_prefetch(x4, buf0, tile, t);

    int i = 0;
    while (tile < NTILES) {
        float* cur = (i & 1) ? buf1 : buf0;
        float* nxt = (i & 1) ? buf0 : buf1;
        float4* cur4 = (float4*)cur;
        const int ntile = tile + grid_stride;

        // nxt was TMA-stored two iterations ago; ensure engine finished reading it
        if (use_tma && t == 0)
            asm volatile("cp.async.bulk.wait_group.read 0;\n" ::: "memory");
        __syncthreads();

        if (ntile < NTILES) {
            k3_prefetch(x4, nxt, ntile, t);
            asm volatile("cp.async.wait_group 1;\n");
        } else {
            asm volatile("cp.async.wait_group 0;\n");
        }
        __syncthreads();

        // yb partial dots: p = pixel (0..31), q = channel octant (0..7)
        {
            const int p = t & 31, q = t >> 5;
            float acc = 0.f;
            const float* tp_ = cur + (q * 32) * TP + p;
            const float* vp  = sv + q * 32;
#pragma unroll
            for (int c = 0; c < 32; c++) acc += vp[c] * tp_[c * TP];
            part[q * TP + p] = acc;
        }
        __syncthreads();
        if (t < TP) {
            float yb = b0;
#pragma unroll
            for (int q = 0; q < 8; q++) yb += part[q * TP + t];
            sy[t] = 1.f / (1.f + expf(-yb));
        }
        __syncthreads();

        const int base4 = tile * TP4;
        if (use_tma) {
            // transform IN PLACE, then one 32KB TMA bulk store of the whole tile
#pragma unroll
            for (int j = 0; j < 8; j++) {
                int i4 = t + j * 256;
                int c = i4 >> 3, p4 = i4 & 7;
                float4 xv = cur4[i4];
                const float gv = sg[c];
                const int p = p4 * 4;
                float4 o;
                o.x = (gv + sy[p + 0]) * xv.x;
                o.y = (gv + sy[p + 1]) * xv.y;
                o.z = (gv + sy[p + 2]) * xv.z;
                o.w = (gv + sy[p + 3]) * xv.w;
                cur4[i4] = o;
            }
            __syncthreads();
            if (t == 0) {
                asm volatile("fence.proxy.async.shared::cta;\n" ::: "memory");
                unsigned su = (unsigned)__cvta_generic_to_shared(cur);
                asm volatile(
                    "cp.async.bulk.tensor.2d.global.shared::cta.tile.bulk_group "
                    "[%0, {%1, %2}], [%3];\n"
                    :: "l"(&tmap), "r"(tile * TP), "r"(0), "r"(su) : "memory");
                asm volatile("cp.async.bulk.commit_group;\n" ::: "memory");
            }
        } else {
            // fallback: champion STG path
#pragma unroll
            for (int j = 0; j < 8; j++) {
                int i4 = t + j * 256;
                int c = i4 >> 3, p4 = i4 & 7;
                float4 xv = cur4[i4];
                const float gv = sg[c];
                const int p = p4 * 4;
                float4 o;
                o.x = (gv + sy[p + 0]) * xv.x;
                o.y = (gv + sy[p + 1]) * xv.y;
                o.z = (gv + sy[p + 2]) * xv.z;
                o.w = (gv + sy[p + 3]) * xv.w;
                out4[(size_t)c * HW4 + base4 + p4] = o;
            }
            __syncthreads();
        }
        tile = ntile;
        i++;
    }
    if (use_tma && t == 0)
        asm volatile("cp.async.bulk.wait_group 0;\n" ::: "memory");
}

// ---------------- Launch ----------------------------------------------------------
extern "C" void kernel_launch(void* const* d_in, const int* in_sizes, int n_in,
                              void* d_out, int out_size) {
    const float* x    = (const float*)d_in[0];
    const float* cv1w = (const float*)d_in[1];
    const float* cv1b = (const float*)d_in[2];
    // d_in[3], d_in[4] = ch_cv2_w/b : mathematically unused (softmax over size-1 dim)
    const float* cv3w = (const float*)d_in[5];
    const float* cv3b = (const float*)d_in[6];
    const float* lng  = (const float*)d_in[7];
    const float* lnb  = (const float*)d_in[8];
    const float* sp1w = (const float*)d_in[9];
    const float* sp1b = (const float*)d_in[10];
    const float* sp2w = (const float*)d_in[11];
    const float* sp2b = (const float*)d_in[12];

    int nsm = 148;
    cudaDeviceGetAttribute(&nsm, cudaDevAttrMultiProcessorCount, 0);
    const int grid3 = nsm * 3;   // 3 CTAs/SM

    // Build TMA store descriptor for out viewed as [C][HW]; box = [C rows][TP pixels].
    CUtensorMap tmap;
    memset(&tmap, 0, sizeof(tmap));
    int use_tma = 0;
    {
        typedef CUresult (*PFN_enc)(CUtensorMap*, CUtensorMapDataType, cuuint32_t, void*,
                                    const cuuint64_t*, const cuuint64_t*, const cuuint32_t*,
                                    const cuuint32_t*, CUtensorMapInterleave, CUtensorMapSwizzle,
                                    CUtensorMapL2promotion, CUtensorMapFloatOOBfill);
        void* sym = nullptr;
        cudaDriverEntryPointQueryResult qr = cudaDriverEntryPointSymbolNotFound;
        if (cudaGetDriverEntryPoint("cuTensorMapEncodeTiled", &sym, cudaEnableDefault, &qr)
                == cudaSuccess && sym != nullptr) {
            cuuint64_t dims[2]    = {(cuuint64_t)HWn, (cuuint64_t)C};
            cuuint64_t strides[1] = {(cuuint64_t)HWn * sizeof(float)};  // 1 MB between channels
            cuuint32_t box[2]     = {(cuuint32_t)TP, (cuuint32_t)C};
            cuuint32_t est[2]     = {1, 1};
            PFN_enc fn = (PFN_enc)sym;
            if (fn(&tmap, CU_TENSOR_MAP_DATA_TYPE_FLOAT32, 2, d_out, dims, strides, box, est,
                   CU_TENSOR_MAP_INTERLEAVE_NONE, CU_TENSOR_MAP_SWIZZLE_NONE,
                   CU_TENSOR_MAP_L2_PROMOTION_L2_128B, CU_TENSOR_MAP_FLOAT_OOB_FILL_NONE)
                    == CUDA_SUCCESS)
                use_tma = 1;
        }
    }

    dim3 g1(SEGS, C);
    k1_sums<<<g1, 256>>>((const float4*)x);
    k2_scalars<<<1, 256>>>(cv1w, cv1b, cv3w, cv3b, lng, lnb, sp1w, sp1b, sp2w, sp2b);

    const int smem_bytes = (2 * TILE_F + C + C + 256 + TP) * (int)sizeof(float);
    cudaFuncSetAttribute(k3_out, cudaFuncAttributeMaxDynamicSharedMemorySize, smem_bytes);
    k3_out<<<grid3, 256, smem_bytes>>>((const float4*)x, (float4*)d_out, grid3, tmap, use_tma);
}

// round 10
// speedup vs baseline: 1.1823x; 1.1823x over previous
#include <cuda_runtime.h>

#define C    256
#define CH   128
#define HWn  262144
#define HW4  65536
#define SEGS 16
#define SEG_F4 4096   // HW4 / SEGS
#define EPS  1e-5f

// k3 tiling: 32 pixels per tile, depth-2 cp.async pipeline, 3 CTAs/SM
#define TP     32
#define TP4    8
#define TILE_F  (C * TP)       // 8192 floats = 32 KB
#define NTILES  (HWn / TP)     // 8192 tiles

__device__ float d_partials[C * SEGS];
__device__ float d_gv[2 * C + 1];   // [0,C) = g, [C,2C) = v, [2C] = b0
__device__ unsigned d_flag;         // zero-init at load; reset by k1 each call

// ---------------- Kernel 1: per-channel spatial sums ------------------------------
__global__ void k1_sums(const float4* __restrict__ x4) {
    const int c = blockIdx.y, seg = blockIdx.x, t = threadIdx.x;
    if (c == 0 && seg == 0 && t == 0) d_flag = 0u;   // reset scalar-ready flag
    const float4* xc = x4 + (size_t)c * HW4 + (size_t)seg * SEG_F4;
    float s = 0.f;
#pragma unroll
    for (int j = 0; j < 16; j++) {
        float4 u = xc[t + j * 256];
        s += (u.x + u.y) + (u.z + u.w);
    }
    __shared__ float red[256];
    red[t] = s;
    __syncthreads();
    for (int off = 128; off > 0; off >>= 1) {
        if (t < off) red[t] += red[t + off];
        __syncthreads();
    }
    if (t == 0) d_partials[c * SEGS + seg] = red[0];
}

// ---------------- Kernel 3: fused scalars + pipelined yb + output -----------------
__device__ __forceinline__ void k3_prefetch(const float4* __restrict__ x4,
                                            float* buf, int tile, int t) {
    if (tile < NTILES) {
        unsigned dst_base = (unsigned)__cvta_generic_to_shared(buf);
        const int base4 = tile * TP4;
#pragma unroll
        for (int j = 0; j < 8; j++) {
            int i4 = t + j * 256;
            int c = i4 >> 3, p4 = i4 & 7;
            const float4* src = x4 + (size_t)c * HW4 + base4 + p4;
            unsigned dst = dst_base + i4 * 16;
            asm volatile("cp.async.cg.shared.global [%0], [%1], 16;\n" :: "r"(dst), "l"(src));
        }
    }
    asm volatile("cp.async.commit_group;\n");   // empty group OK when out of range
}

__global__ __launch_bounds__(256, 3)
void k3_out(const float4* __restrict__ x4, float4* __restrict__ out4, int gs,
            const float* __restrict__ cv1w, const float* __restrict__ cv1b,
            const float* __restrict__ cv3w, const float* __restrict__ cv3b,
            const float* __restrict__ lng,  const float* __restrict__ lnb,
            const float* __restrict__ sp1w, const float* __restrict__ sp1b,
            const float* __restrict__ sp2w, const float* __restrict__ sp2b) {
    extern __shared__ float sm[];
    float* buf0 = sm;                    // TILE_F
    float* buf1 = sm + TILE_F;           // TILE_F
    float* sv   = sm + 2 * TILE_F;       // C
    float* sg   = sv + C;                // C
    float* scr0 = sg + C;                // 256 (k2 scratch, then `part`)
    float* scr1 = scr0 + 256;            // 256 (k2 scratch)
    float* sy   = scr1 + 256;            // TP

    const int t = threadIdx.x;

    // ---- start the pipeline immediately: two tiles in flight ----
    int tile = blockIdx.x;
    k3_prefetch(x4, buf0, tile, t);
    k3_prefetch(x4, buf1, tile + gs, t);

    // ---- CTA 0 computes scalars (overlapped with everyone's prefetches) ----
    if (blockIdx.x == 0) {
        // S[c]
        {
            float s = 0.f;
#pragma unroll
            for (int j = 0; j < SEGS; j++) s += d_partials[t * SEGS + j];
            scr0[t] = s;
        }
        __syncthreads();
        // layer 1: ybuf (t<128) / s2pre (t>=128) -> scr1
        if (t < CH) {
            float a = 0.f;
            for (int c = 0; c < C; c++) a += cv1w[t * C + c] * scr0[c];
            scr1[t] = a + (float)HWn * cv1b[t];
        } else {
            const int u = t - CH;
            float a = 0.f;
            for (int c = 0; c < C; c++) a += sp2w[u * C + c] * scr0[c];
            scr1[t] = a * (1.f / (float)HWn) + sp2b[u];
        }
        __syncthreads();
        // z = cv3w . ybuf + b
        float zv = cv3b[t];
        for (int c = 0; c < CH; c++) zv += cv3w[t * CH + c] * scr1[c];
        // LayerNorm over C
        scr0[t] = zv;
        __syncthreads();
        for (int off = 128; off > 0; off >>= 1) {
            if (t < off) scr0[t] += scr0[t + off];
            __syncthreads();
        }
        const float mu = scr0[0] * (1.f / (float)C);
        __syncthreads();
        scr0[t] = zv * zv;
        __syncthreads();
        for (int off = 128; off > 0; off >>= 1) {
            if (t < off) scr0[t] += scr0[t + off];
            __syncthreads();
        }
        const float var = scr0[0] * (1.f / (float)C) - mu * mu;
        __syncthreads();
        const float zn = (zv - mu) * rsqrtf(var + EPS) * lng[t] + lnb[t];
        d_gv[t] = 1.f / (1.f + expf(-zn));                       // g
        // softmax over s2pre
        scr0[t] = (t < CH) ? scr1[CH + t] : -1e30f;
        __syncthreads();
        for (int off = 128; off > 0; off >>= 1) {
            if (t < off) scr0[t] = fmaxf(scr0[t], scr0[t + off]);
            __syncthreads();
        }
        const float mx = scr0[0];
        __syncthreads();
        scr0[t] = (t < CH) ? expf(scr1[CH + t] - mx) : 0.f;
        __syncthreads();
        for (int off = 128; off > 0; off >>= 1) {
            if (t < off) scr0[t] += scr0[t + off];
            __syncthreads();
        }
        const float denom = scr0[0];
        __syncthreads();
        if (t < CH) scr1[CH + t] = expf(scr1[CH + t] - mx) / denom;   // wsm
        __syncthreads();
        // v, b0
        {
            float vv = 0.f;
            for (int c_ = 0; c_ < CH; c_++) vv += scr1[CH + c_] * sp1w[c_ * C + t];
            d_gv[C + t] = vv;
        }
        if (t == 0) {
            float bb = 0.f;
            for (int c_ = 0; c_ < CH; c_++) bb += scr1[CH + c_] * sp1b[c_];
            d_gv[2 * C] = bb;
        }
        __threadfence();
        __syncthreads();
        if (t == 0) atomicExch(&d_flag, 1u);
    }

    // ---- all CTAs: wait for scalars, then stage g/v/b0 ----
    if (t == 0) {
        while (atomicAdd(&d_flag, 0u) == 0u) __nanosleep(100);
        __threadfence();
    }
    __syncthreads();
    sg[t] = d_gv[t];
    sv[t] = d_gv[C + t];
    const float b0 = d_gv[2 * C];

    // ---- main pipelined loop ----
    int i = 0;
    for (; tile < NTILES; tile += gs, i++) {
        float* cur = (i & 1) ? buf1 : buf0;
        float4* cur4 = (float4*)cur;

        asm volatile("cp.async.wait_group 1;\n");   // tile i's group landed
        __syncthreads();

        // yb partial dots: p = pixel (0..31), q = channel octant (0..7)
        {
            const int p = t & 31, q = t >> 5;
            float acc = 0.f;
            const float* tp_ = cur + (q * 32) * TP + p;
            const float* vp  = sv + q * 32;
#pragma unroll
            for (int c = 0; c < 32; c++) acc += vp[c] * tp_[c * TP];
            scr0[q * TP + p] = acc;
        }
        __syncthreads();
        if (t < TP) {
            float yb = b0;
#pragma unroll
            for (int q = 0; q < 8; q++) yb += scr0[q * TP + t];
            sy[t] = 1.f / (1.f + expf(-yb));
        }
        __syncthreads();

        // out = (g[c] + sigmoid(yb[p])) * x
        const int base4 = tile * TP4;
#pragma unroll
        for (int j = 0; j < 8; j++) {
            int i4 = t + j * 256;
            int c = i4 >> 3, p4 = i4 & 7;
            float4 xv = cur4[i4];
            const float gv = sg[c];
            const int p = p4 * 4;
            float4 o;
            o.x = (gv + sy[p + 0]) * xv.x;
            o.y = (gv + sy[p + 1]) * xv.y;
            o.z = (gv + sy[p + 2]) * xv.z;
            o.w = (gv + sy[p + 3]) * xv.w;
            out4[(size_t)c * HW4 + base4 + p4] = o;
        }
        __syncthreads();                               // cur consumed
        k3_prefetch(x4, cur, tile + 2 * gs, t);        // refill cur for tile i+2
    }
}

// ---------------- Launch ----------------------------------------------------------
extern "C" void kernel_launch(void* const* d_in, const int* in_sizes, int n_in,
                              void* d_out, int out_size) {
    const float* x    = (const float*)d_in[0];
    const float* cv1w = (const float*)d_in[1];
    const float* cv1b = (const float*)d_in[2];
    // d_in[3], d_in[4] = ch_cv2_w/b : mathematically unused (softmax over size-1 dim)
    const float* cv3w = (const float*)d_in[5];
    const float* cv3b = (const float*)d_in[6];
    const float* lng  = (const float*)d_in[7];
    const float* lnb  = (const float*)d_in[8];
    const float* sp1w = (const float*)d_in[9];
    const float* sp1b = (const float*)d_in[10];
    const float* sp2w = (const float*)d_in[11];
    const float* sp2b = (const float*)d_in[12];

    int nsm = 148;
    cudaDeviceGetAttribute(&nsm, cudaDevAttrMultiProcessorCount, 0);
    const int grid3 = nsm * 3;   // 3 CTAs/SM, all co-resident (spin-wait safe)

    dim3 g1(SEGS, C);
    k1_sums<<<g1, 256>>>((const float4*)x);

    const int smem_bytes = (2 * TILE_F + C + C + 256 + 256 + TP) * (int)sizeof(float);
    cudaFuncSetAttribute(k3_out, cudaFuncAttributeMaxDynamicSharedMemorySize, smem_bytes);
    k3_out<<<grid3, 256, smem_bytes>>>((const float4*)x, (float4*)d_out, grid3,
                                       cv1w, cv1b, cv3w, cv3b, lng, lnb,
                                       sp1w, sp1b, sp2w, sp2b);
}